// round 12
// baseline (speedup 1.0000x reference)
#include <cuda_runtime.h>
#include <cuda_bf16.h>

#define BB 8
#define LL 200
#define HH 128
#define NHH 4
#define DHH 32
#define SCALE 0.17677669529663688f   // 1/sqrt(32)

#define WSTRIDE 132                   // smem W row stride (16B-aligned, conflict-free LDS.128)
#define PROJ_SMEM ((HH * WSTRIDE + HH * 36) * 4)   // 86016 bytes

__device__ float g_Q[BB * LL * HH];
__device__ float g_K[BB * LL * HH];
__device__ float g_V[BB * LL * HH];

__device__ __forceinline__ void cpasync16(void* smem_ptr, const void* gptr) {
    unsigned sa = (unsigned)__cvta_generic_to_shared(smem_ptr);
    asm volatile("cp.async.cg.shared.global [%0], [%1], 16;\n" :: "r"(sa), "l"(gptr));
}

// ---------------------------------------------------------------------------
// Projection: grid (50,3) = 150 CTAs (one wave), 256 threads.
// ALL of W prefetched via cp.async (overlapped with X transpose); single sync;
// then one uninterrupted 128-k FFMA loop.
// ---------------------------------------------------------------------------
__global__ __launch_bounds__(256) void proj_kernel(
    const float* __restrict__ queries, const float* __restrict__ keys,
    const float* __restrict__ apK, const float* __restrict__ apV,
    const float* __restrict__ Qw, const float* __restrict__ Kw,
    const float* __restrict__ Vw,
    const float* __restrict__ Qb, const float* __restrict__ Kb,
    const float* __restrict__ Vb)
{
    extern __shared__ float smem[];
    float* sW  = smem;                  // [col][k] stride WSTRIDE  (66KB)
    float* sXT = smem + HH * WSTRIDE;   // [k][row(+pad36)]         (18KB)

    const int tid = threadIdx.x;
    const int col = tid & 127;
    const int rg  = tid >> 7;
    const int g   = blockIdx.y;
    const int row0 = blockIdx.x * 32;

    const float* X = (g == 0) ? queries : keys;
    const float* W = (g == 0) ? Qw : (g == 1) ? Kw : Vw;
    const float4* W4 = reinterpret_cast<const float4*>(W);

    // 1) issue full-W prefetch: 4096 x 16B cp.async (16 per thread)
    #pragma unroll
    for (int t = 0; t < 16; t++) {
        const int idx = t * 256 + tid;     // 0..4095
        const int cw = idx >> 5, k4 = idx & 31;
        cpasync16(&sW[cw * WSTRIDE + k4 * 4], W4 + cw * 32 + k4);
    }
    asm volatile("cp.async.commit_group;\n" ::: "memory");

    // 2) X transpose (overlaps with W fetch)
    {
        const float4* X4 = reinterpret_cast<const float4*>(X) + row0 * 32;
        #pragma unroll
        for (int t = 0; t < 4; t++) {
            const int i = t * 256 + tid;
            const int row = i >> 5, k4 = i & 31;
            const float4 v = X4[i];
            sXT[(4 * k4 + 0) * 36 + row] = v.x;
            sXT[(4 * k4 + 1) * 36 + row] = v.y;
            sXT[(4 * k4 + 2) * 36 + row] = v.z;
            sXT[(4 * k4 + 3) * 36 + row] = v.w;
        }
    }

    asm volatile("cp.async.wait_group 0;\n" ::: "memory");
    __syncthreads();

    // 3) compute: 128 k, W via LDS.128 every 4 k, X via broadcast LDS.128
    float acc[16];
    #pragma unroll
    for (int j = 0; j < 16; j++) acc[j] = 0.0f;
    const int xbase = rg * 16;
    const float* wpc = &sW[col * WSTRIDE];

    #pragma unroll 4
    for (int k4 = 0; k4 < 32; k4++) {
        const float4 w4 = *reinterpret_cast<const float4*>(wpc + k4 * 4);
        #pragma unroll
        for (int j = 0; j < 4; j++) {
            const float w = (j == 0) ? w4.x : (j == 1) ? w4.y : (j == 2) ? w4.z : w4.w;
            const int kk = k4 * 4 + j;
            const float4 x0 = *reinterpret_cast<const float4*>(&sXT[kk * 36 + xbase + 0]);
            const float4 x1 = *reinterpret_cast<const float4*>(&sXT[kk * 36 + xbase + 4]);
            const float4 x2 = *reinterpret_cast<const float4*>(&sXT[kk * 36 + xbase + 8]);
            const float4 x3 = *reinterpret_cast<const float4*>(&sXT[kk * 36 + xbase + 12]);
            acc[0]  += x0.x * w;  acc[1]  += x0.y * w;
            acc[2]  += x0.z * w;  acc[3]  += x0.w * w;
            acc[4]  += x1.x * w;  acc[5]  += x1.y * w;
            acc[6]  += x1.z * w;  acc[7]  += x1.w * w;
            acc[8]  += x2.x * w;  acc[9]  += x2.y * w;
            acc[10] += x2.z * w;  acc[11] += x2.w * w;
            acc[12] += x3.x * w;  acc[13] += x3.y * w;
            acc[14] += x3.z * w;  acc[15] += x3.w * w;
        }
    }

    if (g == 0) {
        const float b = Qb[col];
        #pragma unroll
        for (int j = 0; j < 16; j++) {
            const int row = row0 + xbase + j;
            g_Q[row * HH + col] = (acc[j] + b) * SCALE;
        }
    } else if (g == 1) {
        const float b = Kb[col];
        #pragma unroll
        for (int j = 0; j < 16; j++) {
            const int row = row0 + xbase + j;
            g_K[row * HH + col] = acc[j] + b + apK[row * HH + col];
        }
    } else {
        const float b = Vb[col];
        #pragma unroll
        for (int j = 0; j < 16; j++) {
            const int row = row0 + xbase + j;
            g_V[row * HH + col] = acc[j] + b + apV[row * HH + col];
        }
    }
}

__device__ __forceinline__ float dot4(float4 q, float4 a, float4 b) {
    return q.x * (a.x + b.x) + q.y * (a.y + b.y)
         + q.z * (a.z + b.z) + q.w * (a.w + b.w);
}
__device__ __forceinline__ float red8(float s) {
    s += __shfl_down_sync(0xffffffffu, s, 4);
    s += __shfl_down_sync(0xffffffffu, s, 2);
    s += __shfl_down_sync(0xffffffffu, s, 1);
    return s;
}

// ---------------------------------------------------------------------------
// Attention (R11 winner, UNCHANGED): 1D grid 1600, globally descending l.
// ---------------------------------------------------------------------------
__global__ __launch_bounds__(256, 5) void attn_kernel(
    const float* __restrict__ tK, const float* __restrict__ tV,
    const int*   __restrict__ tmask, float* __restrict__ out)
{
    const int bid = blockIdx.x;
    const int l = LL - 1 - (bid >> 3);
    const int b = bid & 7;
    const int tid  = threadIdx.x;
    const int w    = tid >> 5;
    const int lane = tid & 31;

    __shared__ float4 sQ[32];
    __shared__ float  sP[NHH * LL];
    __shared__ float4 sRed[8 * 32];

    const bool masked = (tmask[b * LL + l] != 0);

    if (tid < 32)
        sQ[tid] = reinterpret_cast<const float4*>(g_Q)[(b * LL + l) * 32 + tid];
    __syncthreads();

    // ---------------- Phase A: logits ----------------
    if (!masked) {
        const float4* tK4 = reinterpret_cast<const float4*>(tK) + (size_t)(b * LL + l) * LL * 32 + lane;
        const float4* K4  = reinterpret_cast<const float4*>(g_K) + (size_t)b * LL * 32 + lane;
        const float4 q = sQ[lane];
        const int head = lane >> 3;
        const bool wr = ((lane & 7) == 0);
        int m = w;
        for (; m + 24 <= l; m += 32) {
            const float4 t0 = __ldcs(tK4 + (size_t)(m)      * 32);
            const float4 t1 = __ldcs(tK4 + (size_t)(m + 8)  * 32);
            const float4 t2 = __ldcs(tK4 + (size_t)(m + 16) * 32);
            const float4 t3 = __ldcs(tK4 + (size_t)(m + 24) * 32);
            const float4 k0 = K4[(m)      * 32];
            const float4 k1 = K4[(m + 8)  * 32];
            const float4 k2 = K4[(m + 16) * 32];
            const float4 k3 = K4[(m + 24) * 32];
            float s0 = red8(dot4(q, t0, k0));
            float s1 = red8(dot4(q, t1, k1));
            float s2 = red8(dot4(q, t2, k2));
            float s3 = red8(dot4(q, t3, k3));
            if (wr) {
                sP[head * LL + m]      = s0;
                sP[head * LL + m + 8]  = s1;
                sP[head * LL + m + 16] = s2;
                sP[head * LL + m + 24] = s3;
            }
        }
        for (; m <= l; m += 8) {
            const float4 t = __ldcs(tK4 + (size_t)m * 32);
            const float4 k = K4[m * 32];
            const float s = red8(dot4(q, t, k));
            if (wr) sP[head * LL + m] = s;
        }
    }
    __syncthreads();

    // ---------------- Phase B: softmax ----------------
    if (masked) {
        const float invL = 1.0f / (float)LL;
        for (int i = tid; i < NHH * LL; i += 256) sP[i] = invL;
    } else if (w < NHH) {
        const int h = w;
        float mx = -3.4e38f;
        for (int m = lane; m <= l; m += 32) mx = fmaxf(mx, sP[h * LL + m]);
        #pragma unroll
        for (int off = 16; off; off >>= 1)
            mx = fmaxf(mx, __shfl_xor_sync(0xffffffffu, mx, off));
        float sum = 0.0f;
        for (int m = lane; m <= l; m += 32) {
            const float e = __expf(sP[h * LL + m] - mx);
            sP[h * LL + m] = e;
            sum += e;
        }
        #pragma unroll
        for (int off = 16; off; off >>= 1)
            sum += __shfl_xor_sync(0xffffffffu, sum, off);
        const float inv = 1.0f / sum;
        for (int m = lane; m <= l; m += 32) sP[h * LL + m] *= inv;
    }
    __syncthreads();

    // ---------------- Phase C: output ----------------
    {
        const int mEnd = masked ? (LL - 1) : l;
        const float4* tV4 = reinterpret_cast<const float4*>(tV) + (size_t)(b * LL + l) * LL * 32 + lane;
        const float4* V4  = reinterpret_cast<const float4*>(g_V) + (size_t)b * LL * 32 + lane;
        const int head = lane >> 3;
        float4 acc = make_float4(0.f, 0.f, 0.f, 0.f);
        int m = w;
        for (; m + 24 <= mEnd; m += 32) {
            const float p0 = sP[head * LL + m];
            const float p1 = sP[head * LL + m + 8];
            const float p2 = sP[head * LL + m + 16];
            const float p3 = sP[head * LL + m + 24];
            const float4 t0 = __ldcs(tV4 + (size_t)(m)      * 32);
            const float4 t1 = __ldcs(tV4 + (size_t)(m + 8)  * 32);
            const float4 t2 = __ldcs(tV4 + (size_t)(m + 16) * 32);
            const float4 t3 = __ldcs(tV4 + (size_t)(m + 24) * 32);
            const float4 v0 = V4[(m)      * 32];
            const float4 v1 = V4[(m + 8)  * 32];
            const float4 v2 = V4[(m + 16) * 32];
            const float4 v3 = V4[(m + 24) * 32];
            acc.x += p0 * (t0.x + v0.x) + p1 * (t1.x + v1.x)
                   + p2 * (t2.x + v2.x) + p3 * (t3.x + v3.x);
            acc.y += p0 * (t0.y + v0.y) + p1 * (t1.y + v1.y)
                   + p2 * (t2.y + v2.y) + p3 * (t3.y + v3.y);
            acc.z += p0 * (t0.z + v0.z) + p1 * (t1.z + v1.z)
                   + p2 * (t2.z + v2.z) + p3 * (t3.z + v3.z);
            acc.w += p0 * (t0.w + v0.w) + p1 * (t1.w + v1.w)
                   + p2 * (t2.w + v2.w) + p3 * (t3.w + v3.w);
        }
        for (; m <= mEnd; m += 8) {
            const float p = sP[head * LL + m];
            const float4 t = __ldcs(tV4 + (size_t)m * 32);
            const float4 v = V4[m * 32];
            acc.x += p * (t.x + v.x);
            acc.y += p * (t.y + v.y);
            acc.z += p * (t.z + v.z);
            acc.w += p * (t.w + v.w);
        }
        sRed[w * 32 + lane] = acc;
    }
    __syncthreads();

    if (tid < 32) {
        float4 r = sRed[tid];
        #pragma unroll
        for (int w2 = 1; w2 < 8; w2++) {
            const float4 a = sRed[w2 * 32 + tid];
            r.x += a.x; r.y += a.y; r.z += a.z; r.w += a.w;
        }
        reinterpret_cast<float4*>(out)[(b * LL + l) * 32 + tid] = r;
    }
}

extern "C" void kernel_launch(void* const* d_in, const int* in_sizes, int n_in,
                              void* d_out, int out_size)
{
    const float* queries = (const float*)d_in[0];
    const float* keys    = (const float*)d_in[1];
    const int*   tmask   = (const int*)  d_in[2];
    // d_in[3] = attn_mask (causal triu, analytic -> unused)
    const float* tK      = (const float*)d_in[4];
    const float* tV      = (const float*)d_in[5];
    const float* apK     = (const float*)d_in[6];
    const float* apV     = (const float*)d_in[7];
    const float* Qw      = (const float*)d_in[8];
    const float* Qb      = (const float*)d_in[9];
    const float* Kw      = (const float*)d_in[10];
    const float* Kb      = (const float*)d_in[11];
    const float* Vw      = (const float*)d_in[12];
    const float* Vb      = (const float*)d_in[13];
    float* out = (float*)d_out;

    cudaFuncSetAttribute(proj_kernel,
                         cudaFuncAttributeMaxDynamicSharedMemorySize, PROJ_SMEM);
    proj_kernel<<<dim3(50, 3), 256, PROJ_SMEM>>>(queries, keys, apK, apV,
                                                 Qw, Kw, Vw, Qb, Kb, Vb);
    attn_kernel<<<BB * LL, 256>>>(tK, tV, tmask, out);
}

// round 13
// speedup vs baseline: 1.1047x; 1.1047x over previous
#include <cuda_runtime.h>
#include <cuda_bf16.h>

#define BB 8
#define LL 200
#define HH 128
#define NHH 4
#define DHH 32
#define SCALE 0.17677669529663688f   // 1/sqrt(32)

__device__ float g_Q[BB * LL * HH];
__device__ float g_K[BB * LL * HH];
__device__ float g_V[BB * LL * HH];

__device__ __forceinline__ void cpasync16(void* smem_ptr, const void* gptr) {
    unsigned sa = (unsigned)__cvta_generic_to_shared(smem_ptr);
    asm volatile("cp.async.cg.shared.global [%0], [%1], 16;\n" :: "r"(sa), "l"(gptr));
}

// ---------------------------------------------------------------------------
// Projection (R11 static config, best measured): grid (50,3), 256 thr.
// W staged verbatim with 65-float padded rows, two 64-k halves.
// ---------------------------------------------------------------------------
__global__ __launch_bounds__(256) void proj_kernel(
    const float* __restrict__ queries, const float* __restrict__ keys,
    const float* __restrict__ apK, const float* __restrict__ apV,
    const float* __restrict__ Qw, const float* __restrict__ Kw,
    const float* __restrict__ Vw,
    const float* __restrict__ Qb, const float* __restrict__ Kb,
    const float* __restrict__ Vb)
{
    __shared__ float sXT[HH * 36];
    __shared__ float sW[HH * 65];

    const int tid = threadIdx.x;
    const int col = tid & 127;
    const int rg  = tid >> 7;
    const int g   = blockIdx.y;
    const int row0 = blockIdx.x * 32;

    const float* X = (g == 0) ? queries : keys;
    const float* W = (g == 0) ? Qw : (g == 1) ? Kw : Vw;
    const float4* W4 = reinterpret_cast<const float4*>(W);

    {
        const float4* X4 = reinterpret_cast<const float4*>(X) + row0 * 32;
        #pragma unroll
        for (int t = 0; t < 4; t++) {
            const int i = t * 256 + tid;
            const int row = i >> 5, k4 = i & 31;
            const float4 v = X4[i];
            sXT[(4 * k4 + 0) * 36 + row] = v.x;
            sXT[(4 * k4 + 1) * 36 + row] = v.y;
            sXT[(4 * k4 + 2) * 36 + row] = v.z;
            sXT[(4 * k4 + 3) * 36 + row] = v.w;
        }
    }

    float acc[16];
    #pragma unroll
    for (int j = 0; j < 16; j++) acc[j] = 0.0f;

    const int xbase = rg * 16;

    #pragma unroll
    for (int half = 0; half < 2; half++) {
        __syncthreads();
        #pragma unroll
        for (int t = 0; t < 8; t++) {
            const int idx = t * 256 + tid;
            const int cw = idx >> 4, k4 = idx & 15;
            const float4 v = W4[cw * 32 + half * 16 + k4];
            float* d = &sW[cw * 65 + k4 * 4];
            d[0] = v.x; d[1] = v.y; d[2] = v.z; d[3] = v.w;
        }
        __syncthreads();

        const float* wp = &sW[col * 65];
        #pragma unroll 8
        for (int k = 0; k < 64; k++) {
            const float w = wp[k];
            const int kk = half * 64 + k;
            const float4 x0 = *reinterpret_cast<const float4*>(&sXT[kk * 36 + xbase + 0]);
            const float4 x1 = *reinterpret_cast<const float4*>(&sXT[kk * 36 + xbase + 4]);
            const float4 x2 = *reinterpret_cast<const float4*>(&sXT[kk * 36 + xbase + 8]);
            const float4 x3 = *reinterpret_cast<const float4*>(&sXT[kk * 36 + xbase + 12]);
            acc[0]  += x0.x * w;  acc[1]  += x0.y * w;
            acc[2]  += x0.z * w;  acc[3]  += x0.w * w;
            acc[4]  += x1.x * w;  acc[5]  += x1.y * w;
            acc[6]  += x1.z * w;  acc[7]  += x1.w * w;
            acc[8]  += x2.x * w;  acc[9]  += x2.y * w;
            acc[10] += x2.z * w;  acc[11] += x2.w * w;
            acc[12] += x3.x * w;  acc[13] += x3.y * w;
            acc[14] += x3.z * w;  acc[15] += x3.w * w;
        }
    }

    if (g == 0) {
        const float b = Qb[col];
        #pragma unroll
        for (int j = 0; j < 16; j++) {
            const int row = row0 + xbase + j;
            g_Q[row * HH + col] = (acc[j] + b) * SCALE;
        }
    } else if (g == 1) {
        const float b = Kb[col];
        #pragma unroll
        for (int j = 0; j < 16; j++) {
            const int row = row0 + xbase + j;
            g_K[row * HH + col] = acc[j] + b + apK[row * HH + col];
        }
    } else {
        const float b = Vb[col];
        #pragma unroll
        for (int j = 0; j < 16; j++) {
            const int row = row0 + xbase + j;
            g_V[row * HH + col] = acc[j] + b + apV[row * HH + col];
        }
    }
}

__device__ __forceinline__ float dot4(float4 q, float4 a, float4 b) {
    return q.x * (a.x + b.x) + q.y * (a.y + b.y)
         + q.z * (a.z + b.z) + q.w * (a.w + b.w);
}
__device__ __forceinline__ float red8(float s) {
    s += __shfl_down_sync(0xffffffffu, s, 4);
    s += __shfl_down_sync(0xffffffffu, s, 2);
    s += __shfl_down_sync(0xffffffffu, s, 1);
    return s;
}

// ---------------------------------------------------------------------------
// Attention (R11 winner + cp.async tV-head prefetch overlapping softmax):
// 1D grid 1600, globally descending l.
// ---------------------------------------------------------------------------
__global__ __launch_bounds__(256, 5) void attn_kernel(
    const float* __restrict__ tK, const float* __restrict__ tV,
    const int*   __restrict__ tmask, float* __restrict__ out)
{
    const int bid = blockIdx.x;
    const int l = LL - 1 - (bid >> 3);
    const int b = bid & 7;
    const int tid  = threadIdx.x;
    const int w    = tid >> 5;
    const int lane = tid & 31;

    __shared__ float4 sQ[32];
    __shared__ float  sP[NHH * LL];
    __shared__ float4 sRed[8 * 32];
    __shared__ float4 sTV[32 * 32];    // first 32 tV rows (16KB)

    const bool masked = (tmask[b * LL + l] != 0);

    if (tid < 32)
        sQ[tid] = reinterpret_cast<const float4*>(g_Q)[(b * LL + l) * 32 + tid];
    __syncthreads();

    // ---------------- Phase A: logits ----------------
    if (!masked) {
        const float4* tK4 = reinterpret_cast<const float4*>(tK) + (size_t)(b * LL + l) * LL * 32 + lane;
        const float4* K4  = reinterpret_cast<const float4*>(g_K) + (size_t)b * LL * 32 + lane;
        const float4 q = sQ[lane];
        const int head = lane >> 3;
        const bool wr = ((lane & 7) == 0);
        int m = w;
        for (; m + 24 <= l; m += 32) {
            const float4 t0 = __ldcs(tK4 + (size_t)(m)      * 32);
            const float4 t1 = __ldcs(tK4 + (size_t)(m + 8)  * 32);
            const float4 t2 = __ldcs(tK4 + (size_t)(m + 16) * 32);
            const float4 t3 = __ldcs(tK4 + (size_t)(m + 24) * 32);
            const float4 k0 = K4[(m)      * 32];
            const float4 k1 = K4[(m + 8)  * 32];
            const float4 k2 = K4[(m + 16) * 32];
            const float4 k3 = K4[(m + 24) * 32];
            float s0 = red8(dot4(q, t0, k0));
            float s1 = red8(dot4(q, t1, k1));
            float s2 = red8(dot4(q, t2, k2));
            float s3 = red8(dot4(q, t3, k3));
            if (wr) {
                sP[head * LL + m]      = s0;
                sP[head * LL + m + 8]  = s1;
                sP[head * LL + m + 16] = s2;
                sP[head * LL + m + 24] = s3;
            }
        }
        for (; m <= l; m += 8) {
            const float4 t = __ldcs(tK4 + (size_t)m * 32);
            const float4 k = K4[m * 32];
            const float s = red8(dot4(q, t, k));
            if (wr) sP[head * LL + m] = s;
        }
    }
    __syncthreads();

    // issue tV head prefetch (rows 0..31) -- overlaps Phase B, zero reg cost
    {
        const float4* tVrow = reinterpret_cast<const float4*>(tV) + (size_t)(b * LL + l) * LL * 32;
        #pragma unroll
        for (int t = 0; t < 4; t++) {
            const int idx = t * 256 + tid;     // 0..1023 = 32 rows x 32 chunks
            cpasync16(&sTV[idx], tVrow + idx);
        }
        asm volatile("cp.async.commit_group;\n" ::: "memory");
    }

    // ---------------- Phase B: softmax ----------------
    if (masked) {
        const float invL = 1.0f / (float)LL;
        for (int i = tid; i < NHH * LL; i += 256) sP[i] = invL;
    } else if (w < NHH) {
        const int h = w;
        float mx = -3.4e38f;
        for (int m = lane; m <= l; m += 32) mx = fmaxf(mx, sP[h * LL + m]);
        #pragma unroll
        for (int off = 16; off; off >>= 1)
            mx = fmaxf(mx, __shfl_xor_sync(0xffffffffu, mx, off));
        float sum = 0.0f;
        for (int m = lane; m <= l; m += 32) {
            const float e = __expf(sP[h * LL + m] - mx);
            sP[h * LL + m] = e;
            sum += e;
        }
        #pragma unroll
        for (int off = 16; off; off >>= 1)
            sum += __shfl_xor_sync(0xffffffffu, sum, off);
        const float inv = 1.0f / sum;
        for (int m = lane; m <= l; m += 32) sP[h * LL + m] *= inv;
    }
    asm volatile("cp.async.wait_group 0;\n" ::: "memory");
    __syncthreads();

    // ---------------- Phase C: output ----------------
    {
        const int mEnd = masked ? (LL - 1) : l;
        const float4* tV4 = reinterpret_cast<const float4*>(tV) + (size_t)(b * LL + l) * LL * 32 + lane;
        const float4* V4  = reinterpret_cast<const float4*>(g_V) + (size_t)b * LL * 32 + lane;
        const int head = lane >> 3;
        float4 acc = make_float4(0.f, 0.f, 0.f, 0.f);

        // rows 0..31 from the prefetched smem tile
        #pragma unroll
        for (int j = 0; j < 4; j++) {
            const int m = w + 8 * j;
            if (m <= mEnd) {
                const float p = sP[head * LL + m];
                const float4 t = sTV[m * 32 + lane];
                const float4 v = V4[m * 32];
                acc.x += p * (t.x + v.x);
                acc.y += p * (t.y + v.y);
                acc.z += p * (t.z + v.z);
                acc.w += p * (t.w + v.w);
            }
        }

        int m = 32 + w;
        for (; m + 24 <= mEnd; m += 32) {
            const float p0 = sP[head * LL + m];
            const float p1 = sP[head * LL + m + 8];
            const float p2 = sP[head * LL + m + 16];
            const float p3 = sP[head * LL + m + 24];
            const float4 t0 = __ldcs(tV4 + (size_t)(m)      * 32);
            const float4 t1 = __ldcs(tV4 + (size_t)(m + 8)  * 32);
            const float4 t2 = __ldcs(tV4 + (size_t)(m + 16) * 32);
            const float4 t3 = __ldcs(tV4 + (size_t)(m + 24) * 32);
            const float4 v0 = V4[(m)      * 32];
            const float4 v1 = V4[(m + 8)  * 32];
            const float4 v2 = V4[(m + 16) * 32];
            const float4 v3 = V4[(m + 24) * 32];
            acc.x += p0 * (t0.x + v0.x) + p1 * (t1.x + v1.x)
                   + p2 * (t2.x + v2.x) + p3 * (t3.x + v3.x);
            acc.y += p0 * (t0.y + v0.y) + p1 * (t1.y + v1.y)
                   + p2 * (t2.y + v2.y) + p3 * (t3.y + v3.y);
            acc.z += p0 * (t0.z + v0.z) + p1 * (t1.z + v1.z)
                   + p2 * (t2.z + v2.z) + p3 * (t3.z + v3.z);
            acc.w += p0 * (t0.w + v0.w) + p1 * (t1.w + v1.w)
                   + p2 * (t2.w + v2.w) + p3 * (t3.w + v3.w);
        }
        for (; m <= mEnd; m += 8) {
            const float p = sP[head * LL + m];
            const float4 t = __ldcs(tV4 + (size_t)m * 32);
            const float4 v = V4[m * 32];
            acc.x += p * (t.x + v.x);
            acc.y += p * (t.y + v.y);
            acc.z += p * (t.z + v.z);
            acc.w += p * (t.w + v.w);
        }
        sRed[w * 32 + lane] = acc;
    }
    __syncthreads();

    if (tid < 32) {
        float4 r = sRed[tid];
        #pragma unroll
        for (int w2 = 1; w2 < 8; w2++) {
            const float4 a = sRed[w2 * 32 + tid];
            r.x += a.x; r.y += a.y; r.z += a.z; r.w += a.w;
        }
        reinterpret_cast<float4*>(out)[(b * LL + l) * 32 + tid] = r;
    }
}

extern "C" void kernel_launch(void* const* d_in, const int* in_sizes, int n_in,
                              void* d_out, int out_size)
{
    const float* queries = (const float*)d_in[0];
    const float* keys    = (const float*)d_in[1];
    const int*   tmask   = (const int*)  d_in[2];
    // d_in[3] = attn_mask (causal triu, analytic -> unused)
    const float* tK      = (const float*)d_in[4];
    const float* tV      = (const float*)d_in[5];
    const float* apK     = (const float*)d_in[6];
    const float* apV     = (const float*)d_in[7];
    const float* Qw      = (const float*)d_in[8];
    const float* Qb      = (const float*)d_in[9];
    const float* Kw      = (const float*)d_in[10];
    const float* Kb      = (const float*)d_in[11];
    const float* Vw      = (const float*)d_in[12];
    const float* Vb      = (const float*)d_in[13];
    float* out = (float*)d_out;

    proj_kernel<<<dim3(50, 3), 256>>>(queries, keys, apK, apV, Qw, Kw, Vw, Qb, Kb, Vb);
    attn_kernel<<<BB * LL, 256>>>(tK, tV, tmask, out);
}

// round 14
// speedup vs baseline: 1.1056x; 1.0008x over previous
#include <cuda_runtime.h>
#include <cuda_bf16.h>

#define BB 8
#define LL 200
#define HH 128
#define NHH 4
#define DHH 32
#define SCALE 0.17677669529663688f   // 1/sqrt(32)

__device__ float g_Q[BB * LL * HH];
__device__ float g_K[BB * LL * HH];
__device__ float g_V[BB * LL * HH];

__device__ __forceinline__ void cpasync16(void* smem_ptr, const void* gptr) {
    unsigned sa = (unsigned)__cvta_generic_to_shared(smem_ptr);
    asm volatile("cp.async.cg.shared.global [%0], [%1], 16;\n" :: "r"(sa), "l"(gptr));
}

// ---------------------------------------------------------------------------
// Projection (R11 static config, best measured): grid (50,3), 256 thr.
// ---------------------------------------------------------------------------
__global__ __launch_bounds__(256) void proj_kernel(
    const float* __restrict__ queries, const float* __restrict__ keys,
    const float* __restrict__ apK, const float* __restrict__ apV,
    const float* __restrict__ Qw, const float* __restrict__ Kw,
    const float* __restrict__ Vw,
    const float* __restrict__ Qb, const float* __restrict__ Kb,
    const float* __restrict__ Vb)
{
    __shared__ float sXT[HH * 36];
    __shared__ float sW[HH * 65];

    const int tid = threadIdx.x;
    const int col = tid & 127;
    const int rg  = tid >> 7;
    const int g   = blockIdx.y;
    const int row0 = blockIdx.x * 32;

    const float* X = (g == 0) ? queries : keys;
    const float* W = (g == 0) ? Qw : (g == 1) ? Kw : Vw;
    const float4* W4 = reinterpret_cast<const float4*>(W);

    {
        const float4* X4 = reinterpret_cast<const float4*>(X) + row0 * 32;
        #pragma unroll
        for (int t = 0; t < 4; t++) {
            const int i = t * 256 + tid;
            const int row = i >> 5, k4 = i & 31;
            const float4 v = X4[i];
            sXT[(4 * k4 + 0) * 36 + row] = v.x;
            sXT[(4 * k4 + 1) * 36 + row] = v.y;
            sXT[(4 * k4 + 2) * 36 + row] = v.z;
            sXT[(4 * k4 + 3) * 36 + row] = v.w;
        }
    }

    float acc[16];
    #pragma unroll
    for (int j = 0; j < 16; j++) acc[j] = 0.0f;

    const int xbase = rg * 16;

    #pragma unroll
    for (int half = 0; half < 2; half++) {
        __syncthreads();
        #pragma unroll
        for (int t = 0; t < 8; t++) {
            const int idx = t * 256 + tid;
            const int cw = idx >> 4, k4 = idx & 15;
            const float4 v = W4[cw * 32 + half * 16 + k4];
            float* d = &sW[cw * 65 + k4 * 4];
            d[0] = v.x; d[1] = v.y; d[2] = v.z; d[3] = v.w;
        }
        __syncthreads();

        const float* wp = &sW[col * 65];
        #pragma unroll 8
        for (int k = 0; k < 64; k++) {
            const float w = wp[k];
            const int kk = half * 64 + k;
            const float4 x0 = *reinterpret_cast<const float4*>(&sXT[kk * 36 + xbase + 0]);
            const float4 x1 = *reinterpret_cast<const float4*>(&sXT[kk * 36 + xbase + 4]);
            const float4 x2 = *reinterpret_cast<const float4*>(&sXT[kk * 36 + xbase + 8]);
            const float4 x3 = *reinterpret_cast<const float4*>(&sXT[kk * 36 + xbase + 12]);
            acc[0]  += x0.x * w;  acc[1]  += x0.y * w;
            acc[2]  += x0.z * w;  acc[3]  += x0.w * w;
            acc[4]  += x1.x * w;  acc[5]  += x1.y * w;
            acc[6]  += x1.z * w;  acc[7]  += x1.w * w;
            acc[8]  += x2.x * w;  acc[9]  += x2.y * w;
            acc[10] += x2.z * w;  acc[11] += x2.w * w;
            acc[12] += x3.x * w;  acc[13] += x3.y * w;
            acc[14] += x3.z * w;  acc[15] += x3.w * w;
        }
    }

    if (g == 0) {
        const float b = Qb[col];
        #pragma unroll
        for (int j = 0; j < 16; j++) {
            const int row = row0 + xbase + j;
            g_Q[row * HH + col] = (acc[j] + b) * SCALE;
        }
    } else if (g == 1) {
        const float b = Kb[col];
        #pragma unroll
        for (int j = 0; j < 16; j++) {
            const int row = row0 + xbase + j;
            g_K[row * HH + col] = acc[j] + b + apK[row * HH + col];
        }
    } else {
        const float b = Vb[col];
        #pragma unroll
        for (int j = 0; j < 16; j++) {
            const int row = row0 + xbase + j;
            g_V[row * HH + col] = acc[j] + b + apV[row * HH + col];
        }
    }
}

__device__ __forceinline__ float dot4(float4 q, float4 a, float4 b) {
    return q.x * (a.x + b.x) + q.y * (a.y + b.y)
         + q.z * (a.z + b.z) + q.w * (a.w + b.w);
}
__device__ __forceinline__ float red8(float s) {
    s += __shfl_down_sync(0xffffffffu, s, 4);
    s += __shfl_down_sync(0xffffffffu, s, 2);
    s += __shfl_down_sync(0xffffffffu, s, 1);
    return s;
}

// ---------------------------------------------------------------------------
// Attention: 1D grid 1600, descending l. cp.async head prefetch for BOTH
// phases: tK rows 0..31 overlap kernel entry; tV rows 0..31 overlap softmax.
// Shared 16KB sTile buffer recycled between phases.
// ---------------------------------------------------------------------------
__global__ __launch_bounds__(256, 5) void attn_kernel(
    const float* __restrict__ tK, const float* __restrict__ tV,
    const int*   __restrict__ tmask, float* __restrict__ out)
{
    const int bid = blockIdx.x;
    const int l = LL - 1 - (bid >> 3);
    const int b = bid & 7;
    const int tid  = threadIdx.x;
    const int w    = tid >> 5;
    const int lane = tid & 31;

    __shared__ float4 sQ[32];
    __shared__ float  sP[NHH * LL];
    __shared__ float4 sRed[8 * 32];
    __shared__ float4 sTile[32 * 32];   // 16KB: tK head, then tV head

    const bool masked = (tmask[b * LL + l] != 0);

    // issue tK head prefetch (rows 0..31) -- overlaps Q load + entry sync
    if (!masked) {
        const float4* tKrow = reinterpret_cast<const float4*>(tK) + (size_t)(b * LL + l) * LL * 32;
        #pragma unroll
        for (int t = 0; t < 4; t++) {
            const int idx = t * 256 + tid;
            cpasync16(&sTile[idx], tKrow + idx);
        }
        asm volatile("cp.async.commit_group;\n" ::: "memory");
    }

    if (tid < 32)
        sQ[tid] = reinterpret_cast<const float4*>(g_Q)[(b * LL + l) * 32 + tid];
    asm volatile("cp.async.wait_group 0;\n" ::: "memory");
    __syncthreads();

    // ---------------- Phase A: logits ----------------
    if (!masked) {
        const float4* tK4 = reinterpret_cast<const float4*>(tK) + (size_t)(b * LL + l) * LL * 32 + lane;
        const float4* K4  = reinterpret_cast<const float4*>(g_K) + (size_t)b * LL * 32 + lane;
        const float4 q = sQ[lane];
        const int head = lane >> 3;
        const bool wr = ((lane & 7) == 0);

        // rows 0..31 from prefetched smem
        #pragma unroll
        for (int j = 0; j < 4; j++) {
            const int m = w + 8 * j;
            if (m <= l) {
                const float4 t = sTile[m * 32 + lane];
                const float4 k = K4[m * 32];
                const float s = red8(dot4(q, t, k));
                if (wr) sP[head * LL + m] = s;
            }
        }

        int m = 32 + w;
        for (; m + 24 <= l; m += 32) {
            const float4 t0 = __ldcs(tK4 + (size_t)(m)      * 32);
            const float4 t1 = __ldcs(tK4 + (size_t)(m + 8)  * 32);
            const float4 t2 = __ldcs(tK4 + (size_t)(m + 16) * 32);
            const float4 t3 = __ldcs(tK4 + (size_t)(m + 24) * 32);
            const float4 k0 = K4[(m)      * 32];
            const float4 k1 = K4[(m + 8)  * 32];
            const float4 k2 = K4[(m + 16) * 32];
            const float4 k3 = K4[(m + 24) * 32];
            float s0 = red8(dot4(q, t0, k0));
            float s1 = red8(dot4(q, t1, k1));
            float s2 = red8(dot4(q, t2, k2));
            float s3 = red8(dot4(q, t3, k3));
            if (wr) {
                sP[head * LL + m]      = s0;
                sP[head * LL + m + 8]  = s1;
                sP[head * LL + m + 16] = s2;
                sP[head * LL + m + 24] = s3;
            }
        }
        for (; m <= l; m += 8) {
            const float4 t = __ldcs(tK4 + (size_t)m * 32);
            const float4 k = K4[m * 32];
            const float s = red8(dot4(q, t, k));
            if (wr) sP[head * LL + m] = s;
        }
    }
    __syncthreads();   // all reads of sTile (tK head) complete here

    // issue tV head prefetch (rows 0..31) -- overlaps Phase B
    {
        const float4* tVrow = reinterpret_cast<const float4*>(tV) + (size_t)(b * LL + l) * LL * 32;
        #pragma unroll
        for (int t = 0; t < 4; t++) {
            const int idx = t * 256 + tid;
            cpasync16(&sTile[idx], tVrow + idx);
        }
        asm volatile("cp.async.commit_group;\n" ::: "memory");
    }

    // ---------------- Phase B: softmax ----------------
    if (masked) {
        const float invL = 1.0f / (float)LL;
        for (int i = tid; i < NHH * LL; i += 256) sP[i] = invL;
    } else if (w < NHH) {
        const int h = w;
        float mx = -3.4e38f;
        for (int m = lane; m <= l; m += 32) mx = fmaxf(mx, sP[h * LL + m]);
        #pragma unroll
        for (int off = 16; off; off >>= 1)
            mx = fmaxf(mx, __shfl_xor_sync(0xffffffffu, mx, off));
        float sum = 0.0f;
        for (int m = lane; m <= l; m += 32) {
            const float e = __expf(sP[h * LL + m] - mx);
            sP[h * LL + m] = e;
            sum += e;
        }
        #pragma unroll
        for (int off = 16; off; off >>= 1)
            sum += __shfl_xor_sync(0xffffffffu, sum, off);
        const float inv = 1.0f / sum;
        for (int m = lane; m <= l; m += 32) sP[h * LL + m] *= inv;
    }
    asm volatile("cp.async.wait_group 0;\n" ::: "memory");
    __syncthreads();

    // ---------------- Phase C: output ----------------
    {
        const int mEnd = masked ? (LL - 1) : l;
        const float4* tV4 = reinterpret_cast<const float4*>(tV) + (size_t)(b * LL + l) * LL * 32 + lane;
        const float4* V4  = reinterpret_cast<const float4*>(g_V) + (size_t)b * LL * 32 + lane;
        const int head = lane >> 3;
        float4 acc = make_float4(0.f, 0.f, 0.f, 0.f);

        // rows 0..31 from prefetched smem
        #pragma unroll
        for (int j = 0; j < 4; j++) {
            const int m = w + 8 * j;
            if (m <= mEnd) {
                const float p = sP[head * LL + m];
                const float4 t = sTile[m * 32 + lane];
                const float4 v = V4[m * 32];
                acc.x += p * (t.x + v.x);
                acc.y += p * (t.y + v.y);
                acc.z += p * (t.z + v.z);
                acc.w += p * (t.w + v.w);
            }
        }

        int m = 32 + w;
        for (; m + 24 <= mEnd; m += 32) {
            const float p0 = sP[head * LL + m];
            const float p1 = sP[head * LL + m + 8];
            const float p2 = sP[head * LL + m + 16];
            const float p3 = sP[head * LL + m + 24];
            const float4 t0 = __ldcs(tV4 + (size_t)(m)      * 32);
            const float4 t1 = __ldcs(tV4 + (size_t)(m + 8)  * 32);
            const float4 t2 = __ldcs(tV4 + (size_t)(m + 16) * 32);
            const float4 t3 = __ldcs(tV4 + (size_t)(m + 24) * 32);
            const float4 v0 = V4[(m)      * 32];
            const float4 v1 = V4[(m + 8)  * 32];
            const float4 v2 = V4[(m + 16) * 32];
            const float4 v3 = V4[(m + 24) * 32];
            acc.x += p0 * (t0.x + v0.x) + p1 * (t1.x + v1.x)
                   + p2 * (t2.x + v2.x) + p3 * (t3.x + v3.x);
            acc.y += p0 * (t0.y + v0.y) + p1 * (t1.y + v1.y)
                   + p2 * (t2.y + v2.y) + p3 * (t3.y + v3.y);
            acc.z += p0 * (t0.z + v0.z) + p1 * (t1.z + v1.z)
                   + p2 * (t2.z + v2.z) + p3 * (t3.z + v3.z);
            acc.w += p0 * (t0.w + v0.w) + p1 * (t1.w + v1.w)
                   + p2 * (t2.w + v2.w) + p3 * (t3.w + v3.w);
        }
        for (; m <= mEnd; m += 8) {
            const float p = sP[head * LL + m];
            const float4 t = __ldcs(tV4 + (size_t)m * 32);
            const float4 v = V4[m * 32];
            acc.x += p * (t.x + v.x);
            acc.y += p * (t.y + v.y);
            acc.z += p * (t.z + v.z);
            acc.w += p * (t.w + v.w);
        }
        sRed[w * 32 + lane] = acc;
    }
    __syncthreads();

    if (tid < 32) {
        float4 r = sRed[tid];
        #pragma unroll
        for (int w2 = 1; w2 < 8; w2++) {
            const float4 a = sRed[w2 * 32 + tid];
            r.x += a.x; r.y += a.y; r.z += a.z; r.w += a.w;
        }
        reinterpret_cast<float4*>(out)[(b * LL + l) * 32 + tid] = r;
    }
}

extern "C" void kernel_launch(void* const* d_in, const int* in_sizes, int n_in,
                              void* d_out, int out_size)
{
    const float* queries = (const float*)d_in[0];
    const float* keys    = (const float*)d_in[1];
    const int*   tmask   = (const int*)  d_in[2];
    // d_in[3] = attn_mask (causal triu, analytic -> unused)
    const float* tK      = (const float*)d_in[4];
    const float* tV      = (const float*)d_in[5];
    const float* apK     = (const float*)d_in[6];
    const float* apV     = (const float*)d_in[7];
    const float* Qw      = (const float*)d_in[8];
    const float* Qb      = (const float*)d_in[9];
    const float* Kw      = (const float*)d_in[10];
    const float* Kb      = (const float*)d_in[11];
    const float* Vw      = (const float*)d_in[12];
    const float* Vb      = (const float*)d_in[13];
    float* out = (float*)d_out;

    proj_kernel<<<dim3(50, 3), 256>>>(queries, keys, apK, apV, Qw, Kw, Vw, Qb, Kb, Vb);
    attn_kernel<<<BB * LL, 256>>>(tK, tV, tmask, out);
}